// round 16
// baseline (speedup 1.0000x reference)
#include <cuda_runtime.h>
#include <cuda_fp16.h>

#define NU 100000
#define NI 50000
#define NN 150000            // NU + NI
#define NE 3000000
#define DIM 128
#define D4  32               // DIM / 4 (float4 / uint2 chunks per row)

#define SCAN_NB 147          // ceil(NN / 1024); blocks 0..146 run the scan phase
#define SCAT_BLOCKS 4096
#define INIT_BLOCKS 2048

// ---- device scratch (allocation-free requirement) ----
// fp16 embedding buffers: [0]=x, [1]=a1, [2]=a2. (a3 is fused into output.)
__device__ uint2 g_h[3][(size_t)NN * D4];
__device__ int    g_deg[NN];
__device__ float  g_inv[NN];
__device__ int    g_off[NN + 1];
__device__ int    g_cur[NN];
__device__ int    g_csr[NE];
__device__ int    g_part[SCAN_NB];
__device__ int    g_base[SCAN_NB];
__device__ int    g_done;       // scan partials published
__device__ int    g_ready;      // bases ready
__device__ int    g_curdone;    // scan blocks that finished writing off/cur/inv
__device__ int    g_is64;

__device__ __forceinline__ __half2 u2h(unsigned u) {
    return *reinterpret_cast<__half2*>(&u);
}

// ---- per-block dtype detection: int64 edge array has zero high words. ----
__device__ __forceinline__ int detect_is64_block(const int* ei32) {
    int acc = 0;
    #pragma unroll
    for (int j = 0; j < 2; j++) acc |= ei32[2 * ((threadIdx.x & 31) + 32 * j) + 1];
    #pragma unroll
    for (int d = 16; d > 0; d >>= 1) acc |= __shfl_xor_sync(0xffffffffu, acc, d);
    return (acc == 0) ? 1 : 0;
}

// ---- 0) zero deg + reset all sync flags ----
__global__ void k_zero() {
    int i = blockIdx.x * blockDim.x + threadIdx.x;
    if (i < NN) g_deg[i] = 0;
    if (i == 0) { g_done = 0; g_ready = 0; g_curdone = 0; }
}

// ---- 1) degree histogram over dst (dst-only reads, unroll x2);
//         block-local dtype detection, block 0 publishes g_is64. ----
__global__ void k_hist(const void* __restrict__ ei) {
    const int is64 = detect_is64_block((const int*)ei);
    if (blockIdx.x == 0 && threadIdx.x == 0) g_is64 = is64;
    const int T = gridDim.x * blockDim.x;
    int e = blockIdx.x * blockDim.x + threadIdx.x;
    if (is64) {
        const long long* d64 = (const long long*)ei + NE;
        for (; e + T < NE; e += 2 * T) {
            int d0 = (int)d64[e];
            int d1 = (int)d64[e + T];
            if ((unsigned)d0 < NN) atomicAdd(&g_deg[d0], 1);
            if ((unsigned)d1 < NN) atomicAdd(&g_deg[d1], 1);
        }
        for (; e < NE; e += T) {
            int d0 = (int)d64[e];
            if ((unsigned)d0 < NN) atomicAdd(&g_deg[d0], 1);
        }
    } else {
        const int* d32 = (const int*)ei + NE;
        for (; e + T < NE; e += 2 * T) {
            int d0 = d32[e];
            int d1 = d32[e + T];
            if ((unsigned)d0 < NN) atomicAdd(&g_deg[d0], 1);
            if ((unsigned)d1 < NN) atomicAdd(&g_deg[d1], 1);
        }
        for (; e < NE; e += T) {
            int d0 = d32[e];
            if ((unsigned)d0 < NN) atomicAdd(&g_deg[d0], 1);
        }
    }
}

// ---- 2) fused scan + scatter + init (single launch).
//         Blocks 0..146: ordered exclusive scan (1024 nodes each, 4/thread),
//         publish off/cur/inv, bump g_curdone, then fall through to scatter.
//         All other blocks spin on g_curdone, then scatter / init. ----
__global__ void k_build(const void* __restrict__ ei,
                        const float4* __restrict__ u4,
                        const float4* __restrict__ i4) {
    const int bid = blockIdx.x;
    const int t = threadIdx.x;

    if (bid < SCAN_NB) {
        __shared__ int sh[256];
        __shared__ int s_last;
        __shared__ int s_base;
        // --- scan 1024 nodes: 4 consecutive per thread ---
        int base = bid * 1024 + t * 4;
        int v0 = (base + 0 < NN) ? g_deg[base + 0] : 0;
        int v1 = (base + 1 < NN) ? g_deg[base + 1] : 0;
        int v2 = (base + 2 < NN) ? g_deg[base + 2] : 0;
        int v3 = (base + 3 < NN) ? g_deg[base + 3] : 0;
        int i0 = v0, i1 = i0 + v1, i2 = i1 + v2, i3 = i2 + v3;
        sh[t] = i3;
        __syncthreads();
        for (int d = 1; d < 256; d <<= 1) {
            int x = (t >= d) ? sh[t - d] : 0;
            __syncthreads();
            sh[t] += x;
            __syncthreads();
        }
        int excl_t = sh[t] - i3;              // exclusive prefix of thread sums
        int blocksum = sh[255];
        __syncthreads();
        if (t == 0) {
            g_part[bid] = blocksum;
            __threadfence();
            s_last = (atomicAdd(&g_done, 1) == SCAN_NB - 1) ? 1 : 0;
        }
        __syncthreads();
        if (s_last) {                          // last block scans 147 partials
            int pv = (t < SCAN_NB) ? g_part[t] : 0;
            sh[t] = pv;
            __syncthreads();
            for (int d = 1; d < 256; d <<= 1) {
                int x = (t >= d) ? sh[t - d] : 0;
                __syncthreads();
                sh[t] += x;
                __syncthreads();
            }
            if (t < SCAN_NB) g_base[t] = sh[t] - pv;
            __threadfence();
            if (t == 0) atomicExch(&g_ready, 1);
        }
        if (t == 0) {
            while (atomicAdd(&g_ready, 0) == 0) { }
            s_base = g_base[bid];
        }
        __syncthreads();
        int o = s_base + excl_t;               // ordered exclusive offsets
        int e0 = o, e1 = o + i0, e2 = o + i1, e3 = o + i2;
        if (base + 0 < NN) { g_off[base + 0] = e0; g_cur[base + 0] = e0;
                             g_inv[base + 0] = v0 > 0 ? 1.0f / (float)v0 : 0.0f; }
        if (base + 1 < NN) { g_off[base + 1] = e1; g_cur[base + 1] = e1;
                             g_inv[base + 1] = v1 > 0 ? 1.0f / (float)v1 : 0.0f; }
        if (base + 2 < NN) { g_off[base + 2] = e2; g_cur[base + 2] = e2;
                             g_inv[base + 2] = v2 > 0 ? 1.0f / (float)v2 : 0.0f; }
        if (base + 3 < NN) { g_off[base + 3] = e3; g_cur[base + 3] = e3;
                             g_inv[base + 3] = v3 > 0 ? 1.0f / (float)v3 : 0.0f; }
        if (bid == 0 && t == 0) g_off[NN] = NE;
        __threadfence();
        __syncthreads();
        if (t == 0) atomicAdd(&g_curdone, 1);
    }

    // --- barrier: all offsets/cursors published (147 scan blocks done) ---
    if (t == 0) {
        while (atomicAdd(&g_curdone, 0) < SCAN_NB) { }
    }
    __syncthreads();

    if (bid < SCAT_BLOCKS) {
        // --- scatter src indices into CSR slots ---
        const int is64 = g_is64;
        const int T = SCAT_BLOCKS * blockDim.x;
        for (int e = bid * blockDim.x + t; e < NE; e += T) {
            int src, dst;
            if (is64) {
                src = (int)((const long long*)ei)[e];
                dst = (int)((const long long*)ei)[NE + e];
            } else {
                src = ((const int*)ei)[e];
                dst = ((const int*)ei)[NE + e];
            }
            if ((unsigned)dst < NN && (unsigned)src < NN) {
                int pos = atomicAdd(&g_cur[dst], 1);
                g_csr[pos] = src;
            }
        }
    } else {
        // --- init: g_h[0] = fp16(cat(user, item)) ---
        const int n4 = NN * D4;
        const int u_n4 = NU * D4;
        const int stride = INIT_BLOCKS * blockDim.x;
        for (int i = (bid - SCAT_BLOCKS) * blockDim.x + t; i < n4; i += stride) {
            float4 v = (i < u_n4) ? u4[i] : i4[i - u_n4];
            __half2 a = __floats2half2_rn(v.x, v.y);
            __half2 b = __floats2half2_rn(v.z, v.w);
            uint2 o;
            o.x = *reinterpret_cast<unsigned*>(&a);
            o.y = *reinterpret_cast<unsigned*>(&b);
            g_h[0][i] = o;
        }
    }
}

// ---- helper: accumulate one fp16 chunk (4 halves) into fp32 sums ----
__device__ __forceinline__ void acc4(uint2 v, float& sx, float& sy,
                                     float& sz, float& sw) {
    float2 fa = __half22float2(u2h(v.x));
    float2 fb = __half22float2(u2h(v.y));
    sx += fa.x; sy += fa.y; sz += fb.x; sw += fb.y;
}

// ---- 3) propagation layer. FUSE=1: layer 3 + final combine fused.
//         Warp per node, lane handles 4 dims. Depth-2 HADD2 tree per 4 edges. ----
template<int FUSE>
__global__ void k_layer_t(int in_idx, float4* __restrict__ out4) {
    const uint2* __restrict__ in = g_h[in_idx];

    int warp = (blockIdx.x * blockDim.x + threadIdx.x) >> 5;
    if (warp >= NN) return;
    int lane = threadIdx.x & 31;

    int beg = g_off[warp];
    int end = g_off[warp + 1];

    float sx = 0.f, sy = 0.f, sz = 0.f, sw = 0.f;
    int e = beg;
    for (; e + 3 < end; e += 4) {
        int s0 = g_csr[e];
        int s1 = g_csr[e + 1];
        int s2 = g_csr[e + 2];
        int s3 = g_csr[e + 3];
        uint2 v0 = in[(size_t)s0 * D4 + lane];
        uint2 v1 = in[(size_t)s1 * D4 + lane];
        uint2 v2 = in[(size_t)s2 * D4 + lane];
        uint2 v3 = in[(size_t)s3 * D4 + lane];
        // depth-2 fp16 tree, one fp32 accumulate per 4 edges
        __half2 a = __hadd2(__hadd2(u2h(v0.x), u2h(v1.x)),
                            __hadd2(u2h(v2.x), u2h(v3.x)));
        __half2 b = __hadd2(__hadd2(u2h(v0.y), u2h(v1.y)),
                            __hadd2(u2h(v2.y), u2h(v3.y)));
        float2 fa = __half22float2(a);
        float2 fb = __half22float2(b);
        sx += fa.x; sy += fa.y; sz += fb.x; sw += fb.y;
    }
    for (; e < end; ++e) {                      // tail: exact fp32 adds
        int s = g_csr[e];
        acc4(in[(size_t)s * D4 + lane], sx, sy, sz, sw);
    }

    float idg = g_inv[warp];
    float rx = sx * idg, ry = sy * idg, rz = sz * idg, rw = sw * idg;

    size_t oi = (size_t)warp * D4 + lane;
    if (FUSE) {
        // out = (x + a1 + a2 + a3) / 4 ; x from fp16 g_h[0], a2 == in[oi],
        // a3 == r (registers). All fp16 reads, fp32 accumulate.
        float tx = rx, ty = ry, tz = rz, tw = rw;
        acc4(g_h[0][oi], tx, ty, tz, tw);
        acc4(g_h[1][oi], tx, ty, tz, tw);
        acc4(in[oi],     tx, ty, tz, tw);
        float4 r;
        r.x = tx * 0.25f; r.y = ty * 0.25f; r.z = tz * 0.25f; r.w = tw * 0.25f;
        __stcs(&out4[oi], r);                   // streaming: evict-first, out never re-read
    } else {
        __half2 ha = __floats2half2_rn(rx, ry);
        __half2 hb = __floats2half2_rn(rz, rw);
        uint2 o;
        o.x = *reinterpret_cast<unsigned*>(&ha);
        o.y = *reinterpret_cast<unsigned*>(&hb);
        g_h[in_idx + 1][oi] = o;
    }
}

extern "C" void kernel_launch(void* const* d_in, const int* in_sizes, int n_in,
                              void* d_out, int out_size) {
    const float4* u4  = (const float4*)d_in[0];
    const float4* i4  = (const float4*)d_in[1];
    const void*   ei  = d_in[2];
    float4*       out = (float4*)d_out;

    // CSR build: zero, hist(+detect), fused scan+scatter+init
    k_zero<<<(NN + 255) / 256, 256>>>();
    k_hist<<<4096, 256>>>(ei);
    k_build<<<SCAT_BLOCKS + INIT_BLOCKS, 256>>>(ei, u4, i4);

    // 3 propagation layers (warp per node); layer 3 fused with final combine
    const int layer_blocks = (NN * 32 + 255) / 256;
    k_layer_t<0><<<layer_blocks, 256>>>(0, out);  // x  -> a1
    k_layer_t<0><<<layer_blocks, 256>>>(1, out);  // a1 -> a2
    k_layer_t<1><<<layer_blocks, 256>>>(2, out);  // a2 -> out (fused)
}